// round 14
// baseline (speedup 1.0000x reference)
#include <cuda_runtime.h>
#include <cuda_fp16.h>
#include <math.h>
#include <stdint.h>

#define BSZ   4
#define CCH   256
#define HIDD  128
#define NPIX  4096
#define L2E   1.4426950408889634f

// ---------------- scratch ---------------------------------------------------
__device__ __half g_xt [(size_t)BSZ * NPIX * CCH];
__device__ __half g_tht[(size_t)BSZ * NPIX * HIDD];
__device__ __half g_phi[(size_t)BSZ * NPIX * HIDD];
__device__ __half g_gh [(size_t)BSZ * HIDD * NPIX];
__device__ __half g_agt[(size_t)BSZ * NPIX * HIDD];
__device__ __half g_E16[(size_t)BSZ * NPIX * NPIX];   // E = exp2(S*log2e), fp16
__device__ __half g_whp[HIDD * CCH];
__device__ __half g_wht[HIDD * CCH];                  // w_theta * log2(e)
__device__ __half g_whg[HIDD * CCH];
__device__ __half g_whm[CCH * HIDD];
__device__ float  g_psum[BSZ * 64 * NPIX];            // tile-local col sums of E

// ---------------- PTX helpers ----------------------------------------------
__device__ __forceinline__ uint32_t s2u(const void* p) {
    return (uint32_t)__cvta_generic_to_shared(p);
}
#define CP16(dst, src) \
    asm volatile("cp.async.cg.shared.global [%0], [%1], 16;" :: "r"(dst), "l"(src))
#define CP_COMMIT() asm volatile("cp.async.commit_group;" ::: "memory")
#define CP_WAIT1()  asm volatile("cp.async.wait_group 1;" ::: "memory")
#define CP_WAIT0()  asm volatile("cp.async.wait_group 0;" ::: "memory")

__device__ __forceinline__ void ldsm_x4(uint32_t& r0, uint32_t& r1,
                                        uint32_t& r2, uint32_t& r3, uint32_t a) {
    asm volatile("ldmatrix.sync.aligned.m8n8.x4.shared.b16 {%0,%1,%2,%3}, [%4];"
                 : "=r"(r0), "=r"(r1), "=r"(r2), "=r"(r3) : "r"(a));
}
__device__ __forceinline__ void mma16816(float* d, const uint32_t* a,
                                         uint32_t b0, uint32_t b1) {
    asm volatile(
        "mma.sync.aligned.m16n8k16.row.col.f32.f16.f16.f32 "
        "{%0,%1,%2,%3}, {%4,%5,%6,%7}, {%8,%9}, {%0,%1,%2,%3};"
        : "+f"(d[0]), "+f"(d[1]), "+f"(d[2]), "+f"(d[3])
        : "r"(a[0]), "r"(a[1]), "r"(a[2]), "r"(a[3]), "r"(b0), "r"(b1));
}
__device__ __forceinline__ uint32_t h2ex2(uint32_t x) {
    uint32_t r;
    asm("ex2.approx.f16x2 %0, %1;" : "=r"(r) : "r"(x));
    return r;
}

#define SMS 40

// 64-row tile chunk (warp tiles 32x32)
#define MMA_CHUNK64(as, bs)                                                   \
    do {                                                                      \
        _Pragma("unroll")                                                     \
        for (int kk = 0; kk < 2; ++kk) {                                      \
            uint32_t afr[2][4], bfr[2][4];                                    \
            _Pragma("unroll")                                                 \
            for (int fm = 0; fm < 2; ++fm)                                    \
                ldsm_x4(afr[fm][0], afr[fm][1], afr[fm][2], afr[fm][3],       \
                        s2u(&(as)[(wm + fm * 16 + (lane & 15)) * SMS +        \
                                  kk * 16 + (lane >> 4) * 8]));               \
            _Pragma("unroll")                                                 \
            for (int fp = 0; fp < 2; ++fp)                                    \
                ldsm_x4(bfr[fp][0], bfr[fp][1], bfr[fp][2], bfr[fp][3],       \
                        s2u(&(bs)[(wn + fp * 16 + (lane & 15)) * SMS +        \
                                  kk * 16 + (lane >> 4) * 8]));               \
            _Pragma("unroll")                                                 \
            for (int fm = 0; fm < 2; ++fm)                                    \
                _Pragma("unroll")                                             \
                for (int fn = 0; fn < 4; ++fn)                                \
                    mma16816(acc[fm][fn], afr[fm],                            \
                             bfr[fn >> 1][fn & 1], bfr[fn >> 1][2 + (fn & 1)]); \
        }                                                                     \
    } while (0)

#define ACC_ZERO(NM)                                                          \
    float acc[NM][4][4];                                                      \
    _Pragma("unroll")                                                         \
    for (int i = 0; i < NM; ++i)                                              \
        _Pragma("unroll")                                                     \
        for (int j = 0; j < 4; ++j)                                           \
            _Pragma("unroll")                                                 \
            for (int q = 0; q < 4; ++q) acc[i][j][q] = 0.f

// ===================== generic GEMM, M-tile 64 =============================
__global__ __launch_bounds__(256, 3)
void k_gemm16_64(const __half* __restrict__ A, const __half* __restrict__ B,
                 __half* __restrict__ C, long long sA, long long sB,
                 long long sC, int lda, int ldb, int ldc, int K) {
    __shared__ __half As[2][64 * SMS];
    __shared__ __half Bs[2][128 * SMS];
    int bm = blockIdx.y * 64, bn = blockIdx.x * 128, b = blockIdx.z;
    A += (long long)b * sA; B += (long long)b * sB; C += (long long)b * sC;
    int t = threadIdx.x, lane = t & 31, wid = t >> 5;
    int wm = (wid & 1) * 32, wn = (wid >> 1) * 32;
    ACC_ZERO(2);
    int nk = K / 32;
#pragma unroll 1
    for (int ki = -1; ki < nk; ++ki) {
        int kl = ki + 1;
        if (kl < nk) {
            {
                int r = t >> 2, s = t & 3;
                CP16(s2u(&As[kl & 1][r * SMS + s * 8]),
                     A + (size_t)(bm + r) * lda + kl * 32 + s * 8);
            }
#pragma unroll
            for (int i = 0; i < 2; ++i) {
                int e = t + i * 256, r = e >> 2, s = e & 3;
                CP16(s2u(&Bs[kl & 1][r * SMS + s * 8]),
                     B + (size_t)(bn + r) * ldb + kl * 32 + s * 8);
            }
            CP_COMMIT();
        }
        if (ki < 0) continue;
        if (kl < nk) CP_WAIT1(); else CP_WAIT0();
        __syncthreads();
        const __half* as = As[ki & 1];
        const __half* bs = Bs[ki & 1];
        MMA_CHUNK64(as, bs);
        __syncthreads();
    }
#pragma unroll
    for (int fm = 0; fm < 2; ++fm) {
        int r0 = bm + wm + fm * 16 + (lane >> 2);
#pragma unroll
        for (int fn = 0; fn < 4; ++fn) {
            int c = bn + wn + fn * 8 + (lane & 3) * 2;
            *(__half2*)&C[(size_t)r0 * ldc + c] =
                __floats2half2_rn(acc[fm][fn][0], acc[fm][fn][1]);
            *(__half2*)&C[(size_t)(r0 + 8) * ldc + c] =
                __floats2half2_rn(acc[fm][fn][2], acc[fm][fn][3]);
        }
    }
}

// ===================== phi + theta merged projection (M-tile 64) ===========
__global__ __launch_bounds__(256, 3)
void k_qkvPT64() {
    __shared__ __half As[2][64 * SMS];
    __shared__ __half Bs[2][128 * SMS];
    int which = blockIdx.x, bm = blockIdx.y * 64, b = blockIdx.z;
    const __half* A = g_xt + (size_t)b * NPIX * CCH;
    const __half* B = which ? g_wht : g_whp;
    __half* C = (which ? g_tht : g_phi) + (size_t)b * NPIX * HIDD;
    int t = threadIdx.x, lane = t & 31, wid = t >> 5;
    int wm = (wid & 1) * 32, wn = (wid >> 1) * 32;
    ACC_ZERO(2);
    const int nk = CCH / 32;
#pragma unroll 1
    for (int ki = -1; ki < nk; ++ki) {
        int kl = ki + 1;
        if (kl < nk) {
            {
                int r = t >> 2, s = t & 3;
                CP16(s2u(&As[kl & 1][r * SMS + s * 8]),
                     A + (size_t)(bm + r) * CCH + kl * 32 + s * 8);
            }
#pragma unroll
            for (int i = 0; i < 2; ++i) {
                int e = t + i * 256, r = e >> 2, s = e & 3;
                CP16(s2u(&Bs[kl & 1][r * SMS + s * 8]),
                     B + (size_t)r * CCH + kl * 32 + s * 8);
            }
            CP_COMMIT();
        }
        if (ki < 0) continue;
        if (kl < nk) CP_WAIT1(); else CP_WAIT0();
        __syncthreads();
        const __half* as = As[ki & 1];
        const __half* bs = Bs[ki & 1];
        MMA_CHUNK64(as, bs);
        __syncthreads();
    }
#pragma unroll
    for (int fm = 0; fm < 2; ++fm) {
        int r0 = bm + wm + fm * 16 + (lane >> 2);
#pragma unroll
        for (int fn = 0; fn < 4; ++fn) {
            int c = wn + fn * 8 + (lane & 3) * 2;
            *(__half2*)&C[(size_t)r0 * HIDD + c] =
                __floats2half2_rn(acc[fm][fn][0], acc[fm][fn][1]);
            *(__half2*)&C[(size_t)(r0 + 8) * HIDD + c] =
                __floats2half2_rn(acc[fm][fn][2], acc[fm][fn][3]);
        }
    }
}

// ===================== scores (M-tile 64) -> E + fused col sums ============
#define SCS 136
#define SC_SMEM ((64 + 128) * SCS * 2)

__global__ __launch_bounds__(256, 3)
void k_scores64() {
    extern __shared__ __half sm[];
    __half* As = sm;                 // 64 x SCS  (theta rows n)
    __half* Bs = sm + 64 * SCS;      // 128 x SCS (phi rows m)
    int b = blockIdx.z, n0 = blockIdx.y * 64, m0 = blockIdx.x * 128;
    const __half* At = g_tht + (size_t)b * NPIX * HIDD;
    const __half* Bt = g_phi + (size_t)b * NPIX * HIDD;
    int t = threadIdx.x, lane = t & 31, wid = t >> 5;
    int wm = (wid & 1) * 32, wn = (wid >> 1) * 32;

#pragma unroll
    for (int i = 0; i < 4; ++i) {
        int e = t + i * 256, r = e >> 4, s = e & 15;
        CP16(s2u(&As[r * SCS + s * 8]), At + (size_t)(n0 + r) * HIDD + s * 8);
    }
#pragma unroll
    for (int i = 0; i < 8; ++i) {
        int e = t + i * 256, r = e >> 4, s = e & 15;
        CP16(s2u(&Bs[r * SCS + s * 8]), Bt + (size_t)(m0 + r) * HIDD + s * 8);
    }
    CP_COMMIT();
    ACC_ZERO(2);
    CP_WAIT0();
    __syncthreads();

#pragma unroll
    for (int kk = 0; kk < 8; ++kk) {
        uint32_t afr[2][4], bfr[2][4];
#pragma unroll
        for (int fm = 0; fm < 2; ++fm)
            ldsm_x4(afr[fm][0], afr[fm][1], afr[fm][2], afr[fm][3],
                    s2u(&As[(wm + fm * 16 + (lane & 15)) * SCS +
                            kk * 16 + (lane >> 4) * 8]));
#pragma unroll
        for (int fp = 0; fp < 2; ++fp)
            ldsm_x4(bfr[fp][0], bfr[fp][1], bfr[fp][2], bfr[fp][3],
                    s2u(&Bs[(wn + fp * 16 + (lane & 15)) * SCS +
                            kk * 16 + (lane >> 4) * 8]));
#pragma unroll
        for (int fm = 0; fm < 2; ++fm)
#pragma unroll
            for (int fn = 0; fn < 4; ++fn)
                mma16816(acc[fm][fn], afr[fm],
                         bfr[fn >> 1][fn & 1], bfr[fn >> 1][2 + (fn & 1)]);
    }

    // E = ex2(S') fp16 -> store + per-tile column sums (64 n-rows)
    float sums[8] = {0.f, 0.f, 0.f, 0.f, 0.f, 0.f, 0.f, 0.f};
    __half* Erow = g_E16 + (size_t)b * NPIX * NPIX;
#pragma unroll
    for (int fm = 0; fm < 2; ++fm) {
        int r0 = n0 + wm + fm * 16 + (lane >> 2);
#pragma unroll
        for (int fn = 0; fn < 4; ++fn) {
            int c = m0 + wn + fn * 8 + (lane & 3) * 2;
            __half2 h0 = __floats2half2_rn(acc[fm][fn][0], acc[fm][fn][1]);
            __half2 h1 = __floats2half2_rn(acc[fm][fn][2], acc[fm][fn][3]);
            uint32_t e0 = h2ex2(*(uint32_t*)&h0);
            uint32_t e1 = h2ex2(*(uint32_t*)&h1);
            *(uint32_t*)&Erow[(size_t)r0 * NPIX + c] = e0;
            *(uint32_t*)&Erow[(size_t)(r0 + 8) * NPIX + c] = e1;
            float2 f0 = __half22float2(*(__half2*)&e0);
            float2 f1 = __half22float2(*(__half2*)&e1);
            sums[fn * 2]     += f0.x + f1.x;
            sums[fn * 2 + 1] += f0.y + f1.y;
        }
    }
#pragma unroll
    for (int d = 4; d < 32; d <<= 1)
#pragma unroll
        for (int j = 0; j < 8; ++j)
            sums[j] += __shfl_xor_sync(0xffffffffu, sums[j], d);
    __syncthreads();
    float* red = (float*)sm;        // reuse tile smem (MMA reads done)
    if (lane < 4)
#pragma unroll
        for (int j = 0; j < 8; ++j)
            red[(wid & 1) * 128 + wn + (j >> 1) * 8 + (lane & 3) * 2 + (j & 1)] = sums[j];
    __syncthreads();
    if (t < 128)
        g_psum[((size_t)b * 64 + blockIdx.y) * NPIX + m0 + t] =
            red[t] + red[128 + t];
}

// combine + scale fused: cs[m] = 256/colsum (64 partials), g[b][:,m] *= cs[m].
__global__ void k_combine_scale() {
    int b = blockIdx.y;
    int m = blockIdx.x * 512 + threadIdx.x * 2;
    float s0 = 0.f, s1 = 0.f;
#pragma unroll 8
    for (int c = 0; c < 64; ++c) {
        float2 ps = *(const float2*)&g_psum[((size_t)b * 64 + c) * NPIX + m];
        s0 += ps.x;
        s1 += ps.y;
    }
    __half2 cs2 = __floats2half2_rn(256.f / s0, 256.f / s1);
    __half* gb = g_gh + (size_t)b * HIDD * NPIX + m;
#pragma unroll 4
    for (int c = 0; c < HIDD; ++c) {
        __half2 v = *(__half2*)&gb[(size_t)c * NPIX];
        *(__half2*)&gb[(size_t)c * NPIX] = __hmul2(v, cs2);
    }
}

// ===================== attn_g: pure cp.async A (E) and B (g'), 3-buffered ==
#define AGS 72
#define AG_SMEM (3 * (64 + 128) * AGS * 2)

__global__ __launch_bounds__(256, 2)
void k_attng16() {
    extern __shared__ __half sm[];
    __half* AsA[3] = {sm, sm + 64 * AGS, sm + 2 * 64 * AGS};
    __half* BsA[3] = {sm + 3 * 64 * AGS, sm + (3 * 64 + 128) * AGS,
                      sm + (3 * 64 + 2 * 128) * AGS};
    int b = blockIdx.z, bm = blockIdx.x * 64;
    int t = threadIdx.x, lane = t & 31, wid = t >> 5;
    int wm = (wid & 1) * 32, wn = (wid >> 1) * 32;
    int r4 = t >> 3, s8 = t & 7;
    const __half* Eb = g_E16 + (size_t)b * NPIX * NPIX;
    const __half* Bg = g_gh + (size_t)b * HIDD * NPIX;
    __half* Cc = g_agt + (size_t)b * NPIX * HIDD;
    ACC_ZERO(2);

#pragma unroll
    for (int i = 0; i < 2; ++i)
        CP16(s2u(&AsA[0][(r4 + i * 32) * AGS + s8 * 8]),
             Eb + (size_t)(bm + r4 + i * 32) * NPIX + s8 * 8);
#pragma unroll
    for (int i = 0; i < 4; ++i)
        CP16(s2u(&BsA[0][(r4 + i * 32) * AGS + s8 * 8]),
             Bg + (size_t)(r4 + i * 32) * NPIX + s8 * 8);
    CP_COMMIT();

    int kb = 0;
#pragma unroll 1
    for (int ki = 0; ki < 64; ++ki) {
        int m0 = ki * 64;
        int kb1 = (kb == 2) ? 0 : kb + 1;
        if (ki < 63) {
#pragma unroll
            for (int i = 0; i < 2; ++i)
                CP16(s2u(&AsA[kb1][(r4 + i * 32) * AGS + s8 * 8]),
                     Eb + (size_t)(bm + r4 + i * 32) * NPIX + m0 + 64 + s8 * 8);
#pragma unroll
            for (int i = 0; i < 4; ++i)
                CP16(s2u(&BsA[kb1][(r4 + i * 32) * AGS + s8 * 8]),
                     Bg + (size_t)(r4 + i * 32) * NPIX + m0 + 64 + s8 * 8);
            CP_COMMIT();
        }
        if (ki < 63) CP_WAIT1(); else CP_WAIT0();
        __syncthreads();
        const __half* as = AsA[kb];
        const __half* bs = BsA[kb];
#pragma unroll
        for (int kk = 0; kk < 4; ++kk) {
            uint32_t afr[2][4], bfr[2][4];
#pragma unroll
            for (int fm = 0; fm < 2; ++fm)
                ldsm_x4(afr[fm][0], afr[fm][1], afr[fm][2], afr[fm][3],
                        s2u(&as[(wm + fm * 16 + (lane & 15)) * AGS +
                                kk * 16 + (lane >> 4) * 8]));
#pragma unroll
            for (int fp = 0; fp < 2; ++fp)
                ldsm_x4(bfr[fp][0], bfr[fp][1], bfr[fp][2], bfr[fp][3],
                        s2u(&bs[(wn + fp * 16 + (lane & 15)) * AGS +
                                kk * 16 + (lane >> 4) * 8]));
#pragma unroll
            for (int fm = 0; fm < 2; ++fm)
#pragma unroll
                for (int fn = 0; fn < 4; ++fn)
                    mma16816(acc[fm][fn], afr[fm],
                             bfr[fn >> 1][fn & 1], bfr[fn >> 1][2 + (fn & 1)]);
        }
        kb = kb1;
    }
    const float inv256 = 0.00390625f;
#pragma unroll
    for (int fm = 0; fm < 2; ++fm) {
        int r0 = bm + wm + fm * 16 + (lane >> 2);
#pragma unroll
        for (int fn = 0; fn < 4; ++fn) {
            int c = wn + fn * 8 + (lane & 3) * 2;
            *(__half2*)&Cc[(size_t)r0 * HIDD + c] =
                __floats2half2_rn(acc[fm][fn][0] * inv256, acc[fm][fn][1] * inv256);
            *(__half2*)&Cc[(size_t)(r0 + 8) * HIDD + c] =
                __floats2half2_rn(acc[fm][fn][2] * inv256, acc[fm][fn][3] * inv256);
        }
    }
}

// ===================== mask GEMM + residual (M-tile 64) ====================
__global__ __launch_bounds__(256, 3)
void k_mask64(const float* __restrict__ x, float* __restrict__ out) {
    __shared__ __half As[2][64 * SMS];
    __shared__ __half Bs[2][128 * SMS];
    int bm = blockIdx.y * 64, bn = blockIdx.x * 128, b = blockIdx.z;
    const __half* A = g_whm;
    const __half* B = g_agt + (size_t)b * NPIX * HIDD;
    int t = threadIdx.x, lane = t & 31, wid = t >> 5;
    int wm = (wid & 1) * 32, wn = (wid >> 1) * 32;
    ACC_ZERO(2);
    const int nk = HIDD / 32;
#pragma unroll 1
    for (int ki = -1; ki < nk; ++ki) {
        int kl = ki + 1;
        if (kl < nk) {
            {
                int r = t >> 2, s = t & 3;
                CP16(s2u(&As[kl & 1][r * SMS + s * 8]),
                     A + (size_t)(bm + r) * HIDD + kl * 32 + s * 8);
            }
#pragma unroll
            for (int i = 0; i < 2; ++i) {
                int e = t + i * 256, r = e >> 2, s = e & 3;
                CP16(s2u(&Bs[kl & 1][r * SMS + s * 8]),
                     B + (size_t)(bn + r) * HIDD + kl * 32 + s * 8);
            }
            CP_COMMIT();
        }
        if (ki < 0) continue;
        if (kl < nk) CP_WAIT1(); else CP_WAIT0();
        __syncthreads();
        const __half* as = As[ki & 1];
        const __half* bs = Bs[ki & 1];
        MMA_CHUNK64(as, bs);
        __syncthreads();
    }
#pragma unroll
    for (int fm = 0; fm < 2; ++fm) {
        int r0 = bm + wm + fm * 16 + (lane >> 2);
#pragma unroll
        for (int fn = 0; fn < 4; ++fn) {
            int c = bn + wn + fn * 8 + (lane & 3) * 2;
            size_t o0 = (size_t)b * CCH * NPIX + (size_t)r0 * NPIX + c;
            size_t o1 = o0 + 8ull * NPIX;
            float2 x0 = *(const float2*)&x[o0];
            float2 x1 = *(const float2*)&x[o1];
            *(float2*)&out[o0] = make_float2(acc[fm][fn][0] + x0.x,
                                             acc[fm][fn][1] + x0.y);
            *(float2*)&out[o1] = make_float2(acc[fm][fn][2] + x1.x,
                                             acc[fm][fn][3] + x1.y);
        }
    }
}

// ===================== prep kernels ========================================
__global__ void k_wconv4(const float* __restrict__ a, const float* __restrict__ b,
                         const float* __restrict__ c, const float* __restrict__ d) {
    int i = blockIdx.x * 256 + threadIdx.x;
    int w = i >> 15, j = i & 32767;
    const float* src = w == 0 ? a : (w == 1 ? b : (w == 2 ? c : d));
    __half* dst = w == 0 ? g_whp : (w == 1 ? g_wht : (w == 2 ? g_whg : g_whm));
    float v = src[j];
    if (w == 1) v *= L2E;
    dst[j] = __float2half(v);
}

__global__ void k_xtrans(const float* __restrict__ x) {
    __shared__ float tile[32][33];
    int b = blockIdx.z;
    int n0 = blockIdx.x * 32, c0 = blockIdx.y * 32;
    const float* xb = x + (size_t)b * CCH * NPIX;
    __half* ob = g_xt + (size_t)b * NPIX * CCH;
    int tx = threadIdx.x, ty = threadIdx.y;
#pragma unroll
    for (int i = 0; i < 32; i += 8)
        tile[ty + i][tx] = xb[(size_t)(c0 + ty + i) * NPIX + n0 + tx];
    __syncthreads();
#pragma unroll
    for (int i = 0; i < 32; i += 8)
        ob[(size_t)(n0 + ty + i) * CCH + c0 + tx] = __float2half(tile[tx][ty + i]);
}

// ===================== launcher ============================================
extern "C" void kernel_launch(void* const* d_in, const int* in_sizes, int n_in,
                              void* d_out, int out_size) {
    const float* x       = (const float*)d_in[0];
    const float* w_phi   = (const float*)d_in[1];
    const float* w_theta = (const float*)d_in[2];
    const float* w_g     = (const float*)d_in[3];
    const float* w_mask  = (const float*)d_in[4];
    float* out = (float*)d_out;
    (void)in_sizes; (void)n_in; (void)out_size;

    static int init_done = 0;
    static cudaStream_t s1;
    static cudaEvent_t evRoot, evX, evW, evG;
    if (!init_done) {
        cudaFuncSetAttribute(k_scores64, cudaFuncAttributeMaxDynamicSharedMemorySize,
                             SC_SMEM);
        cudaFuncSetAttribute(k_attng16, cudaFuncAttributeMaxDynamicSharedMemorySize,
                             AG_SMEM);
        cudaStreamCreateWithFlags(&s1, cudaStreamNonBlocking);
        cudaEventCreateWithFlags(&evRoot, cudaEventDisableTiming);
        cudaEventCreateWithFlags(&evX, cudaEventDisableTiming);
        cudaEventCreateWithFlags(&evW, cudaEventDisableTiming);
        cudaEventCreateWithFlags(&evG, cudaEventDisableTiming);
        init_done = 1;
    }

    __half *whg, *xt, *gh;
    cudaGetSymbolAddress((void**)&whg, g_whg);
    cudaGetSymbolAddress((void**)&xt,  g_xt);
    cudaGetSymbolAddress((void**)&gh,  g_gh);

    const long long sX = (long long)NPIX * CCH;
    const long long sH = (long long)NPIX * HIDD;

    // Fork immediately: s1 joins capture off an event recorded before any work.
    cudaEventRecord(evRoot, 0);
    cudaStreamWaitEvent(s1, evRoot, 0);

    // s0: x transpose (critical path)
    k_xtrans<<<dim3(NPIX / 32, CCH / 32, BSZ), dim3(32, 8)>>>(x);
    cudaEventRecord(evX, 0);

    // s1: weight convert (parallel with xtrans), then g projection after xt.
    k_wconv4<<<512, 256, 0, s1>>>(w_phi, w_theta, w_g, w_mask);
    cudaEventRecord(evW, s1);
    cudaStreamWaitEvent(s1, evX, 0);
    k_gemm16_64<<<dim3(NPIX / 128, HIDD / 64, BSZ), 256, 0, s1>>>(
        whg, xt, gh, 0, sX, sH, CCH, CCH, NPIX, CCH);
    cudaEventRecord(evG, s1);

    // s0: phi/theta projection (needs weights from s1), then scores.
    cudaStreamWaitEvent(0, evW, 0);
    k_qkvPT64<<<dim3(2, NPIX / 64, BSZ), 256>>>();
    k_scores64<<<dim3(NPIX / 128, NPIX / 64, BSZ), 256, SC_SMEM>>>();

    // combine_scale writes g_gh -> join on g-projection.
    cudaStreamWaitEvent(0, evG, 0);
    k_combine_scale<<<dim3(NPIX / 512, BSZ), 256>>>();
    k_attng16<<<dim3(NPIX / 64, 1, BSZ), 256, AG_SMEM>>>();
    k_mask64<<<dim3(NPIX / 128, CCH / 64, BSZ), 256>>>(x, out);
}

// round 15
// speedup vs baseline: 1.0896x; 1.0896x over previous
#include <cuda_runtime.h>
#include <cuda_fp16.h>
#include <math.h>
#include <stdint.h>

#define BSZ   4
#define CCH   256
#define HIDD  128
#define NPIX  4096
#define L2E   1.4426950408889634f

// ---------------- scratch ---------------------------------------------------
__device__ __half g_xt [(size_t)BSZ * NPIX * CCH];
__device__ __half g_tht[(size_t)BSZ * NPIX * HIDD];
__device__ __half g_phi[(size_t)BSZ * NPIX * HIDD];
__device__ __half g_gh [(size_t)BSZ * HIDD * NPIX];
__device__ __half g_agt[(size_t)BSZ * NPIX * HIDD];
__device__ __half g_E16[(size_t)BSZ * NPIX * NPIX];   // E = exp2(S*log2e), fp16
__device__ __half g_whp[HIDD * CCH];
__device__ __half g_wht[HIDD * CCH];                  // w_theta * log2(e)
__device__ __half g_whg[HIDD * CCH];
__device__ __half g_whm[CCH * HIDD];
__device__ float  g_psum[BSZ * 64 * NPIX];            // tile-local col sums of E
__device__ __half g_cs[BSZ * NPIX];                   // 256 / colsum

// ---------------- PTX helpers ----------------------------------------------
__device__ __forceinline__ uint32_t s2u(const void* p) {
    return (uint32_t)__cvta_generic_to_shared(p);
}
#define CP16(dst, src) \
    asm volatile("cp.async.cg.shared.global [%0], [%1], 16;" :: "r"(dst), "l"(src))
#define CP_COMMIT() asm volatile("cp.async.commit_group;" ::: "memory")
#define CP_WAIT1()  asm volatile("cp.async.wait_group 1;" ::: "memory")
#define CP_WAIT0()  asm volatile("cp.async.wait_group 0;" ::: "memory")

__device__ __forceinline__ void ldsm_x4(uint32_t& r0, uint32_t& r1,
                                        uint32_t& r2, uint32_t& r3, uint32_t a) {
    asm volatile("ldmatrix.sync.aligned.m8n8.x4.shared.b16 {%0,%1,%2,%3}, [%4];"
                 : "=r"(r0), "=r"(r1), "=r"(r2), "=r"(r3) : "r"(a));
}
__device__ __forceinline__ void mma16816(float* d, const uint32_t* a,
                                         uint32_t b0, uint32_t b1) {
    asm volatile(
        "mma.sync.aligned.m16n8k16.row.col.f32.f16.f16.f32 "
        "{%0,%1,%2,%3}, {%4,%5,%6,%7}, {%8,%9}, {%0,%1,%2,%3};"
        : "+f"(d[0]), "+f"(d[1]), "+f"(d[2]), "+f"(d[3])
        : "r"(a[0]), "r"(a[1]), "r"(a[2]), "r"(a[3]), "r"(b0), "r"(b1));
}
__device__ __forceinline__ uint32_t h2ex2(uint32_t x) {
    uint32_t r;
    asm("ex2.approx.f16x2 %0, %1;" : "=r"(r) : "r"(x));
    return r;
}

#define SMS 40

// 64-row tile chunk (warp tiles 32x32)
#define MMA_CHUNK64(as, bs)                                                   \
    do {                                                                      \
        _Pragma("unroll")                                                     \
        for (int kk = 0; kk < 2; ++kk) {                                      \
            uint32_t afr[2][4], bfr[2][4];                                    \
            _Pragma("unroll")                                                 \
            for (int fm = 0; fm < 2; ++fm)                                    \
                ldsm_x4(afr[fm][0], afr[fm][1], afr[fm][2], afr[fm][3],       \
                        s2u(&(as)[(wm + fm * 16 + (lane & 15)) * SMS +        \
                                  kk * 16 + (lane >> 4) * 8]));               \
            _Pragma("unroll")                                                 \
            for (int fp = 0; fp < 2; ++fp)                                    \
                ldsm_x4(bfr[fp][0], bfr[fp][1], bfr[fp][2], bfr[fp][3],       \
                        s2u(&(bs)[(wn + fp * 16 + (lane & 15)) * SMS +        \
                                  kk * 16 + (lane >> 4) * 8]));               \
            _Pragma("unroll")                                                 \
            for (int fm = 0; fm < 2; ++fm)                                    \
                _Pragma("unroll")                                             \
                for (int fn = 0; fn < 4; ++fn)                                \
                    mma16816(acc[fm][fn], afr[fm],                            \
                             bfr[fn >> 1][fn & 1], bfr[fn >> 1][2 + (fn & 1)]); \
        }                                                                     \
    } while (0)

#define ACC_ZERO(NM)                                                          \
    float acc[NM][4][4];                                                      \
    _Pragma("unroll")                                                         \
    for (int i = 0; i < NM; ++i)                                              \
        _Pragma("unroll")                                                     \
        for (int j = 0; j < 4; ++j)                                           \
            _Pragma("unroll")                                                 \
            for (int q = 0; q < 4; ++q) acc[i][j][q] = 0.f

// ===================== generic GEMM, M-tile 64 =============================
__global__ __launch_bounds__(256, 3)
void k_gemm16_64(const __half* __restrict__ A, const __half* __restrict__ B,
                 __half* __restrict__ C, long long sA, long long sB,
                 long long sC, int lda, int ldb, int ldc, int K) {
    __shared__ __half As[2][64 * SMS];
    __shared__ __half Bs[2][128 * SMS];
    int bm = blockIdx.y * 64, bn = blockIdx.x * 128, b = blockIdx.z;
    A += (long long)b * sA; B += (long long)b * sB; C += (long long)b * sC;
    int t = threadIdx.x, lane = t & 31, wid = t >> 5;
    int wm = (wid & 1) * 32, wn = (wid >> 1) * 32;
    ACC_ZERO(2);
    int nk = K / 32;
#pragma unroll 1
    for (int ki = -1; ki < nk; ++ki) {
        int kl = ki + 1;
        if (kl < nk) {
            {
                int r = t >> 2, s = t & 3;
                CP16(s2u(&As[kl & 1][r * SMS + s * 8]),
                     A + (size_t)(bm + r) * lda + kl * 32 + s * 8);
            }
#pragma unroll
            for (int i = 0; i < 2; ++i) {
                int e = t + i * 256, r = e >> 2, s = e & 3;
                CP16(s2u(&Bs[kl & 1][r * SMS + s * 8]),
                     B + (size_t)(bn + r) * ldb + kl * 32 + s * 8);
            }
            CP_COMMIT();
        }
        if (ki < 0) continue;
        if (kl < nk) CP_WAIT1(); else CP_WAIT0();
        __syncthreads();
        const __half* as = As[ki & 1];
        const __half* bs = Bs[ki & 1];
        MMA_CHUNK64(as, bs);
        __syncthreads();
    }
#pragma unroll
    for (int fm = 0; fm < 2; ++fm) {
        int r0 = bm + wm + fm * 16 + (lane >> 2);
#pragma unroll
        for (int fn = 0; fn < 4; ++fn) {
            int c = bn + wn + fn * 8 + (lane & 3) * 2;
            *(__half2*)&C[(size_t)r0 * ldc + c] =
                __floats2half2_rn(acc[fm][fn][0], acc[fm][fn][1]);
            *(__half2*)&C[(size_t)(r0 + 8) * ldc + c] =
                __floats2half2_rn(acc[fm][fn][2], acc[fm][fn][3]);
        }
    }
}

// ===== phi + theta merged projection (M-tile 64, triple-buffer, 1 barrier) =
__global__ __launch_bounds__(256, 3)
void k_qkvPT64() {
    __shared__ __half As[3][64 * SMS];
    __shared__ __half Bs[3][128 * SMS];
    int which = blockIdx.x, bm = blockIdx.y * 64, b = blockIdx.z;
    const __half* A = g_xt + (size_t)b * NPIX * CCH;
    const __half* B = which ? g_wht : g_whp;
    __half* C = (which ? g_tht : g_phi) + (size_t)b * NPIX * HIDD;
    int t = threadIdx.x, lane = t & 31, wid = t >> 5;
    int wm = (wid & 1) * 32, wn = (wid >> 1) * 32;
    int ra = t >> 2, sa = t & 3;
    ACC_ZERO(2);
    const int nk = CCH / 32;   // 8

    // prologue: chunk 0 -> buffer 0
    CP16(s2u(&As[0][ra * SMS + sa * 8]),
         A + (size_t)(bm + ra) * CCH + sa * 8);
#pragma unroll
    for (int i = 0; i < 2; ++i) {
        int e = t + i * 256, r = e >> 2, s = e & 3;
        CP16(s2u(&Bs[0][r * SMS + s * 8]), B + (size_t)r * CCH + s * 8);
    }
    CP_COMMIT();

    int kb = 0;
#pragma unroll 1
    for (int ki = 0; ki < nk; ++ki) {
        int kb1 = (kb == 2) ? 0 : kb + 1;
        if (ki < nk - 1) {
            CP16(s2u(&As[kb1][ra * SMS + sa * 8]),
                 A + (size_t)(bm + ra) * CCH + (ki + 1) * 32 + sa * 8);
#pragma unroll
            for (int i = 0; i < 2; ++i) {
                int e = t + i * 256, r = e >> 2, s = e & 3;
                CP16(s2u(&Bs[kb1][r * SMS + s * 8]),
                     B + (size_t)r * CCH + (ki + 1) * 32 + s * 8);
            }
            CP_COMMIT();
        }
        if (ki < nk - 1) CP_WAIT1(); else CP_WAIT0();
        __syncthreads();
        const __half* as = As[kb];
        const __half* bs = Bs[kb];
        MMA_CHUNK64(as, bs);
        kb = kb1;
        // single barrier per iter; buffer reused only after the next barrier
    }
#pragma unroll
    for (int fm = 0; fm < 2; ++fm) {
        int r0 = bm + wm + fm * 16 + (lane >> 2);
#pragma unroll
        for (int fn = 0; fn < 4; ++fn) {
            int c = wn + fn * 8 + (lane & 3) * 2;
            *(__half2*)&C[(size_t)r0 * HIDD + c] =
                __floats2half2_rn(acc[fm][fn][0], acc[fm][fn][1]);
            *(__half2*)&C[(size_t)(r0 + 8) * HIDD + c] =
                __floats2half2_rn(acc[fm][fn][2], acc[fm][fn][3]);
        }
    }
}

// ===================== scores (M-tile 64) -> E + fused col sums ============
#define SCS 136
#define SC_SMEM ((64 + 128) * SCS * 2)

__global__ __launch_bounds__(256, 3)
void k_scores64() {
    extern __shared__ __half sm[];
    __half* As = sm;                 // 64 x SCS  (theta rows n)
    __half* Bs = sm + 64 * SCS;      // 128 x SCS (phi rows m)
    int b = blockIdx.z, n0 = blockIdx.y * 64, m0 = blockIdx.x * 128;
    const __half* At = g_tht + (size_t)b * NPIX * HIDD;
    const __half* Bt = g_phi + (size_t)b * NPIX * HIDD;
    int t = threadIdx.x, lane = t & 31, wid = t >> 5;
    int wm = (wid & 1) * 32, wn = (wid >> 1) * 32;

#pragma unroll
    for (int i = 0; i < 4; ++i) {
        int e = t + i * 256, r = e >> 4, s = e & 15;
        CP16(s2u(&As[r * SCS + s * 8]), At + (size_t)(n0 + r) * HIDD + s * 8);
    }
#pragma unroll
    for (int i = 0; i < 8; ++i) {
        int e = t + i * 256, r = e >> 4, s = e & 15;
        CP16(s2u(&Bs[r * SCS + s * 8]), Bt + (size_t)(m0 + r) * HIDD + s * 8);
    }
    CP_COMMIT();
    ACC_ZERO(2);
    CP_WAIT0();
    __syncthreads();

#pragma unroll
    for (int kk = 0; kk < 8; ++kk) {
        uint32_t afr[2][4], bfr[2][4];
#pragma unroll
        for (int fm = 0; fm < 2; ++fm)
            ldsm_x4(afr[fm][0], afr[fm][1], afr[fm][2], afr[fm][3],
                    s2u(&As[(wm + fm * 16 + (lane & 15)) * SCS +
                            kk * 16 + (lane >> 4) * 8]));
#pragma unroll
        for (int fp = 0; fp < 2; ++fp)
            ldsm_x4(bfr[fp][0], bfr[fp][1], bfr[fp][2], bfr[fp][3],
                    s2u(&Bs[(wn + fp * 16 + (lane & 15)) * SCS +
                            kk * 16 + (lane >> 4) * 8]));
#pragma unroll
        for (int fm = 0; fm < 2; ++fm)
#pragma unroll
            for (int fn = 0; fn < 4; ++fn)
                mma16816(acc[fm][fn], afr[fm],
                         bfr[fn >> 1][fn & 1], bfr[fn >> 1][2 + (fn & 1)]);
    }

    float sums[8] = {0.f, 0.f, 0.f, 0.f, 0.f, 0.f, 0.f, 0.f};
    __half* Erow = g_E16 + (size_t)b * NPIX * NPIX;
#pragma unroll
    for (int fm = 0; fm < 2; ++fm) {
        int r0 = n0 + wm + fm * 16 + (lane >> 2);
#pragma unroll
        for (int fn = 0; fn < 4; ++fn) {
            int c = m0 + wn + fn * 8 + (lane & 3) * 2;
            __half2 h0 = __floats2half2_rn(acc[fm][fn][0], acc[fm][fn][1]);
            __half2 h1 = __floats2half2_rn(acc[fm][fn][2], acc[fm][fn][3]);
            uint32_t e0 = h2ex2(*(uint32_t*)&h0);
            uint32_t e1 = h2ex2(*(uint32_t*)&h1);
            *(uint32_t*)&Erow[(size_t)r0 * NPIX + c] = e0;
            *(uint32_t*)&Erow[(size_t)(r0 + 8) * NPIX + c] = e1;
            float2 f0 = __half22float2(*(__half2*)&e0);
            float2 f1 = __half22float2(*(__half2*)&e1);
            sums[fn * 2]     += f0.x + f1.x;
            sums[fn * 2 + 1] += f0.y + f1.y;
        }
    }
#pragma unroll
    for (int d = 4; d < 32; d <<= 1)
#pragma unroll
        for (int j = 0; j < 8; ++j)
            sums[j] += __shfl_xor_sync(0xffffffffu, sums[j], d);
    __syncthreads();
    float* red = (float*)sm;
    if (lane < 4)
#pragma unroll
        for (int j = 0; j < 8; ++j)
            red[(wid & 1) * 128 + wn + (j >> 1) * 8 + (lane & 3) * 2 + (j & 1)] = sums[j];
    __syncthreads();
    if (t < 128)
        g_psum[((size_t)b * 64 + blockIdx.y) * NPIX + m0 + t] =
            red[t] + red[128 + t];
}

// colsum combine only: cs[b][m] = 256 / sum_c psum.  grid 64 x 256 thr.
__global__ void k_colsum() {
    int idx = blockIdx.x * 256 + threadIdx.x;
    int b = idx >> 12, m = idx & 4095;
    float s = 0.f;
#pragma unroll 8
    for (int c = 0; c < 64; ++c)
        s += g_psum[((size_t)b * 64 + c) * NPIX + m];
    g_cs[idx] = __float2half(256.f / s);
}

// g scale: g[b][c][m] *= cs[b][m].  grid 1024 x 256, 8 halves/thread.
__global__ void k_gscale() {
    int i = (blockIdx.x * 256 + threadIdx.x) * 8;   // over BSZ*HIDD*NPIX
    int b = i >> 19;
    int m = i & (NPIX - 1);
    union { uint4 v; __half2 h[4]; } gv, cv, ov;
    gv.v = *(const uint4*)&g_gh[i];
    cv.v = *(const uint4*)&g_cs[b * NPIX + m];
#pragma unroll
    for (int j = 0; j < 4; ++j) ov.h[j] = __hmul2(gv.h[j], cv.h[j]);
    *(uint4*)&g_gh[i] = ov.v;
}

// ===================== attn_g: pure cp.async A (E) and B (g'), 3-buffered ==
#define AGS 72
#define AG_SMEM (3 * (64 + 128) * AGS * 2)

__global__ __launch_bounds__(256, 2)
void k_attng16() {
    extern __shared__ __half sm[];
    __half* AsA[3] = {sm, sm + 64 * AGS, sm + 2 * 64 * AGS};
    __half* BsA[3] = {sm + 3 * 64 * AGS, sm + (3 * 64 + 128) * AGS,
                      sm + (3 * 64 + 2 * 128) * AGS};
    int b = blockIdx.z, bm = blockIdx.x * 64;
    int t = threadIdx.x, lane = t & 31, wid = t >> 5;
    int wm = (wid & 1) * 32, wn = (wid >> 1) * 32;
    int r4 = t >> 3, s8 = t & 7;
    const __half* Eb = g_E16 + (size_t)b * NPIX * NPIX;
    const __half* Bg = g_gh + (size_t)b * HIDD * NPIX;
    __half* Cc = g_agt + (size_t)b * NPIX * HIDD;
    ACC_ZERO(2);

#pragma unroll
    for (int i = 0; i < 2; ++i)
        CP16(s2u(&AsA[0][(r4 + i * 32) * AGS + s8 * 8]),
             Eb + (size_t)(bm + r4 + i * 32) * NPIX + s8 * 8);
#pragma unroll
    for (int i = 0; i < 4; ++i)
        CP16(s2u(&BsA[0][(r4 + i * 32) * AGS + s8 * 8]),
             Bg + (size_t)(r4 + i * 32) * NPIX + s8 * 8);
    CP_COMMIT();

    int kb = 0;
#pragma unroll 1
    for (int ki = 0; ki < 64; ++ki) {
        int m0 = ki * 64;
        int kb1 = (kb == 2) ? 0 : kb + 1;
        if (ki < 63) {
#pragma unroll
            for (int i = 0; i < 2; ++i)
                CP16(s2u(&AsA[kb1][(r4 + i * 32) * AGS + s8 * 8]),
                     Eb + (size_t)(bm + r4 + i * 32) * NPIX + m0 + 64 + s8 * 8);
#pragma unroll
            for (int i = 0; i < 4; ++i)
                CP16(s2u(&BsA[kb1][(r4 + i * 32) * AGS + s8 * 8]),
                     Bg + (size_t)(r4 + i * 32) * NPIX + m0 + 64 + s8 * 8);
            CP_COMMIT();
        }
        if (ki < 63) CP_WAIT1(); else CP_WAIT0();
        __syncthreads();
        const __half* as = AsA[kb];
        const __half* bs = BsA[kb];
#pragma unroll
        for (int kk = 0; kk < 4; ++kk) {
            uint32_t afr[2][4], bfr[2][4];
#pragma unroll
            for (int fm = 0; fm < 2; ++fm)
                ldsm_x4(afr[fm][0], afr[fm][1], afr[fm][2], afr[fm][3],
                        s2u(&as[(wm + fm * 16 + (lane & 15)) * AGS +
                                kk * 16 + (lane >> 4) * 8]));
#pragma unroll
            for (int fp = 0; fp < 2; ++fp)
                ldsm_x4(bfr[fp][0], bfr[fp][1], bfr[fp][2], bfr[fp][3],
                        s2u(&bs[(wn + fp * 16 + (lane & 15)) * AGS +
                                kk * 16 + (lane >> 4) * 8]));
#pragma unroll
            for (int fm = 0; fm < 2; ++fm)
#pragma unroll
                for (int fn = 0; fn < 4; ++fn)
                    mma16816(acc[fm][fn], afr[fm],
                             bfr[fn >> 1][fn & 1], bfr[fn >> 1][2 + (fn & 1)]);
        }
        kb = kb1;
    }
    const float inv256 = 0.00390625f;
#pragma unroll
    for (int fm = 0; fm < 2; ++fm) {
        int r0 = bm + wm + fm * 16 + (lane >> 2);
#pragma unroll
        for (int fn = 0; fn < 4; ++fn) {
            int c = wn + fn * 8 + (lane & 3) * 2;
            *(__half2*)&Cc[(size_t)r0 * HIDD + c] =
                __floats2half2_rn(acc[fm][fn][0] * inv256, acc[fm][fn][1] * inv256);
            *(__half2*)&Cc[(size_t)(r0 + 8) * HIDD + c] =
                __floats2half2_rn(acc[fm][fn][2] * inv256, acc[fm][fn][3] * inv256);
        }
    }
}

// ===================== mask GEMM + residual (M-tile 64) ====================
__global__ __launch_bounds__(256, 3)
void k_mask64(const float* __restrict__ x, float* __restrict__ out) {
    __shared__ __half As[2][64 * SMS];
    __shared__ __half Bs[2][128 * SMS];
    int bm = blockIdx.y * 64, bn = blockIdx.x * 128, b = blockIdx.z;
    const __half* A = g_whm;
    const __half* B = g_agt + (size_t)b * NPIX * HIDD;
    int t = threadIdx.x, lane = t & 31, wid = t >> 5;
    int wm = (wid & 1) * 32, wn = (wid >> 1) * 32;
    ACC_ZERO(2);
    const int nk = HIDD / 32;
#pragma unroll 1
    for (int ki = -1; ki < nk; ++ki) {
        int kl = ki + 1;
        if (kl < nk) {
            {
                int r = t >> 2, s = t & 3;
                CP16(s2u(&As[kl & 1][r * SMS + s * 8]),
                     A + (size_t)(bm + r) * HIDD + kl * 32 + s * 8);
            }
#pragma unroll
            for (int i = 0; i < 2; ++i) {
                int e = t + i * 256, r = e >> 2, s = e & 3;
                CP16(s2u(&Bs[kl & 1][r * SMS + s * 8]),
                     B + (size_t)(bn + r) * HIDD + kl * 32 + s * 8);
            }
            CP_COMMIT();
        }
        if (ki < 0) continue;
        if (kl < nk) CP_WAIT1(); else CP_WAIT0();
        __syncthreads();
        const __half* as = As[ki & 1];
        const __half* bs = Bs[ki & 1];
        MMA_CHUNK64(as, bs);
        __syncthreads();
    }
#pragma unroll
    for (int fm = 0; fm < 2; ++fm) {
        int r0 = bm + wm + fm * 16 + (lane >> 2);
#pragma unroll
        for (int fn = 0; fn < 4; ++fn) {
            int c = bn + wn + fn * 8 + (lane & 3) * 2;
            size_t o0 = (size_t)b * CCH * NPIX + (size_t)r0 * NPIX + c;
            size_t o1 = o0 + 8ull * NPIX;
            float2 x0 = *(const float2*)&x[o0];
            float2 x1 = *(const float2*)&x[o1];
            *(float2*)&out[o0] = make_float2(acc[fm][fn][0] + x0.x,
                                             acc[fm][fn][1] + x0.y);
            *(float2*)&out[o1] = make_float2(acc[fm][fn][2] + x1.x,
                                             acc[fm][fn][3] + x1.y);
        }
    }
}

// ===================== prep kernels ========================================
__global__ void k_wconv4(const float* __restrict__ a, const float* __restrict__ b,
                         const float* __restrict__ c, const float* __restrict__ d) {
    int i = blockIdx.x * 256 + threadIdx.x;
    int w = i >> 15, j = i & 32767;
    const float* src = w == 0 ? a : (w == 1 ? b : (w == 2 ? c : d));
    __half* dst = w == 0 ? g_whp : (w == 1 ? g_wht : (w == 2 ? g_whg : g_whm));
    float v = src[j];
    if (w == 1) v *= L2E;
    dst[j] = __float2half(v);
}

__global__ void k_xtrans(const float* __restrict__ x) {
    __shared__ float tile[32][33];
    int b = blockIdx.z;
    int n0 = blockIdx.x * 32, c0 = blockIdx.y * 32;
    const float* xb = x + (size_t)b * CCH * NPIX;
    __half* ob = g_xt + (size_t)b * NPIX * CCH;
    int tx = threadIdx.x, ty = threadIdx.y;
#pragma unroll
    for (int i = 0; i < 32; i += 8)
        tile[ty + i][tx] = xb[(size_t)(c0 + ty + i) * NPIX + n0 + tx];
    __syncthreads();
#pragma unroll
    for (int i = 0; i < 32; i += 8)
        ob[(size_t)(n0 + ty + i) * CCH + c0 + tx] = __float2half(tile[tx][ty + i]);
}

// ===================== launcher ============================================
extern "C" void kernel_launch(void* const* d_in, const int* in_sizes, int n_in,
                              void* d_out, int out_size) {
    const float* x       = (const float*)d_in[0];
    const float* w_phi   = (const float*)d_in[1];
    const float* w_theta = (const float*)d_in[2];
    const float* w_g     = (const float*)d_in[3];
    const float* w_mask  = (const float*)d_in[4];
    float* out = (float*)d_out;
    (void)in_sizes; (void)n_in; (void)out_size;

    static int init_done = 0;
    static cudaStream_t s1;
    static cudaEvent_t evRoot, evX, evW, evG;
    if (!init_done) {
        cudaFuncSetAttribute(k_scores64, cudaFuncAttributeMaxDynamicSharedMemorySize,
                             SC_SMEM);
        cudaFuncSetAttribute(k_attng16, cudaFuncAttributeMaxDynamicSharedMemorySize,
                             AG_SMEM);
        cudaStreamCreateWithFlags(&s1, cudaStreamNonBlocking);
        cudaEventCreateWithFlags(&evRoot, cudaEventDisableTiming);
        cudaEventCreateWithFlags(&evX, cudaEventDisableTiming);
        cudaEventCreateWithFlags(&evW, cudaEventDisableTiming);
        cudaEventCreateWithFlags(&evG, cudaEventDisableTiming);
        init_done = 1;
    }

    __half *whg, *xt, *gh;
    cudaGetSymbolAddress((void**)&whg, g_whg);
    cudaGetSymbolAddress((void**)&xt,  g_xt);
    cudaGetSymbolAddress((void**)&gh,  g_gh);

    const long long sX = (long long)NPIX * CCH;
    const long long sH = (long long)NPIX * HIDD;

    // Fork immediately: s1 joins capture off an event recorded before any work.
    cudaEventRecord(evRoot, 0);
    cudaStreamWaitEvent(s1, evRoot, 0);

    // s0: x transpose (critical path)
    k_xtrans<<<dim3(NPIX / 32, CCH / 32, BSZ), dim3(32, 8)>>>(x);
    cudaEventRecord(evX, 0);

    // s1: weight convert (parallel with xtrans), then g projection after xt.
    k_wconv4<<<512, 256, 0, s1>>>(w_phi, w_theta, w_g, w_mask);
    cudaEventRecord(evW, s1);
    cudaStreamWaitEvent(s1, evX, 0);
    k_gemm16_64<<<dim3(NPIX / 128, HIDD / 64, BSZ), 256, 0, s1>>>(
        whg, xt, gh, 0, sX, sH, CCH, CCH, NPIX, CCH);
    cudaEventRecord(evG, s1);

    // s0: phi/theta projection (needs weights from s1), then scores.
    cudaStreamWaitEvent(0, evW, 0);
    k_qkvPT64<<<dim3(2, NPIX / 64, BSZ), 256>>>();
    k_scores64<<<dim3(NPIX / 128, NPIX / 64, BSZ), 256, SC_SMEM>>>();
    k_colsum<<<dim3(BSZ * NPIX / 256), 256>>>();

    // gscale writes g_gh -> join on g-projection.
    cudaStreamWaitEvent(0, evG, 0);
    k_gscale<<<1024, 256>>>();
    k_attng16<<<dim3(NPIX / 64, 1, BSZ), 256, AG_SMEM>>>();
    k_mask64<<<dim3(NPIX / 128, CCH / 64, BSZ), 256>>>(x, out);
}